// round 6
// baseline (speedup 1.0000x reference)
#include <cuda_runtime.h>
#include <cuda_bf16.h>
#include <math_constants.h>

// CropSplitGT: out[h, w, n] = data[h, w, n] if (w,h) inside roi box n else 0.
// data (H, W, N) row-major, rois (4, N) = [x1; y1; x2; y2].
//
// Sparse-read, branch-free, register-lean version:
//  - predicated ld.global.cs.v4 with "=f" outputs: when pred is false the
//    regs are garbage, but the blend (mask bits all 0) forces 0 anyway ->
//    no zero-init MOVs, no live-in pressure.
//  - 2 batches of 4 rows: 16 data regs live instead of 32 -> higher occ.

#define HH 512
#define WW 512
#define NN 400
#define N4 (NN / 4)          // 100 float4 per pixel
#define ROW4 (WW * N4)       // 51200 float4 per row
#define H_PER 8              // rows per thread
#define BATCH 4
#define GY (HH / H_PER)      // 64

__device__ __forceinline__ float4 ldg_cs_pred(const float4* __restrict__ p,
                                              unsigned pred)
{
    // Contents are UNDEFINED when pred==0; caller's blend must mask them.
    float4 v;
    asm("{\n\t"
        ".reg .pred %%pp;\n\t"
        "setp.ne.u32 %%pp, %4, 0;\n\t"
        "@%%pp ld.global.cs.v4.f32 {%0, %1, %2, %3}, [%5];\n\t"
        "}"
        : "=f"(v.x), "=f"(v.y), "=f"(v.z), "=f"(v.w)
        : "r"(pred), "l"(p));
    return v;
}

__global__ __launch_bounds__(128) void crop_split_gt_kernel(
    const float4* __restrict__ data,
    const float*  __restrict__ rois,
    float4*       __restrict__ out)
{
    const int tid = blockIdx.x * 128 + threadIdx.x;   // [0, ROW4) exactly
    const int w   = tid / N4;
    const int n4  = tid - w * N4;
    const float wf = (float)w;

    const float4 x1 = __ldg((const float4*)(rois)          + n4);
    const float4 x2 = __ldg((const float4*)(rois + 2 * NN) + n4);
    float4 y1 = __ldg((const float4*)(rois + NN)     + n4);
    float4 y2 = __ldg((const float4*)(rois + 3 * NN) + n4);

    // Fold x-mask into y-range: if w outside [x1,x2], empty the y-range.
    if (!(wf >= x1.x && wf <= x2.x)) y1.x = CUDART_INF_F;
    if (!(wf >= x1.y && wf <= x2.y)) y1.y = CUDART_INF_F;
    if (!(wf >= x1.z && wf <= x2.z)) y1.z = CUDART_INF_F;
    if (!(wf >= x1.w && wf <= x2.w)) y1.w = CUDART_INF_F;

    const int h0 = blockIdx.y * H_PER;
    const long base = (long)h0 * ROW4 + tid;

    #pragma unroll
    for (int b = 0; b < H_PER / BATCH; ++b) {
        float4 v[BATCH];
        unsigned m[BATCH];

        // Phase 1: masks + 4 predicated loads in flight.
        #pragma unroll
        for (int i = 0; i < BATCH; ++i) {
            const float hf = (float)(h0 + b * BATCH + i);
            const unsigned b0 = (hf >= y1.x && hf <= y2.x) ? 1u : 0u;
            const unsigned b1 = (hf >= y1.y && hf <= y2.y) ? 2u : 0u;
            const unsigned b2 = (hf >= y1.z && hf <= y2.z) ? 4u : 0u;
            const unsigned b3 = (hf >= y1.w && hf <= y2.w) ? 8u : 0u;
            m[i] = b0 | b1 | b2 | b3;
            v[i] = ldg_cs_pred(&data[base + (long)(b * BATCH + i) * ROW4], m[i]);
        }

        // Phase 2: blend (zeroes garbage when mask bit clear) + store.
        #pragma unroll
        for (int i = 0; i < BATCH; ++i) {
            float4 r;
            r.x = (m[i] & 1u) ? v[i].x : 0.0f;
            r.y = (m[i] & 2u) ? v[i].y : 0.0f;
            r.z = (m[i] & 4u) ? v[i].z : 0.0f;
            r.w = (m[i] & 8u) ? v[i].w : 0.0f;
            __stcs(&out[base + (long)(b * BATCH + i) * ROW4], r);
        }
    }
}

extern "C" void kernel_launch(void* const* d_in, const int* in_sizes, int n_in,
                              void* d_out, int out_size)
{
    const float4* data = (const float4*)d_in[0];
    const float*  rois = (const float*)d_in[1];
    float4* out = (float4*)d_out;

    dim3 block(128);
    dim3 grid(ROW4 / 128, GY);   // 400 x 64 blocks
    crop_split_gt_kernel<<<grid, block>>>(data, rois, out);
}

// round 7
// speedup vs baseline: 1.2001x; 1.2001x over previous
#include <cuda_runtime.h>
#include <cuda_bf16.h>
#include <math_constants.h>

// CropSplitGT: out[h, w, n] = data[h, w, n] if (w,h) inside roi box n else 0.
// data (H, W, N) row-major, rois (4, N) = [x1; y1; x2; y2].
//
// Sparse-read, branch-free, MLP-8 version with register-lean addressing:
//  - all 8 row-loads predicated (skip read when all 4 ROI components miss)
//  - loads use ONE base pointer + compile-time immediate offsets ("n"
//    constraint) so no per-load 64-bit address regs are materialized
//  - "=f" outputs: garbage when pred false; blend masks force 0 anyway.

#define HH 512
#define WW 512
#define NN 400
#define N4 (NN / 4)            // 100 float4 per pixel
#define ROW4 (WW * N4)         // 51200 float4 per row
#define ROWB 819200L           // row stride in BYTES (ROW4 * 16)
#define H_PER 8                // rows per thread (MLP 8)
#define GY (HH / H_PER)        // 64

// Predicated 128-bit streaming load at [base + literal byte offset].
#define LDG_CS_PRED_OFF(dst, pred, base, I)                              \
    asm("{\n\t"                                                          \
        ".reg .pred %%pp;\n\t"                                           \
        "setp.ne.u32 %%pp, %4, 0;\n\t"                                   \
        "@%%pp ld.global.cs.v4.f32 {%0, %1, %2, %3}, [%5 + %6];\n\t"     \
        "}"                                                              \
        : "=f"((dst).x), "=f"((dst).y), "=f"((dst).z), "=f"((dst).w)     \
        : "r"(pred), "l"(base), "n"((I) * ROWB))

__global__ __launch_bounds__(128) void crop_split_gt_kernel(
    const float4* __restrict__ data,
    const float*  __restrict__ rois,
    float4*       __restrict__ out)
{
    const int tid = blockIdx.x * 128 + threadIdx.x;   // [0, ROW4) exactly
    const int w   = tid / N4;
    const int n4  = tid - w * N4;
    const float wf = (float)w;

    const float4 x1 = __ldg((const float4*)(rois)          + n4);
    const float4 x2 = __ldg((const float4*)(rois + 2 * NN) + n4);
    float4 y1 = __ldg((const float4*)(rois + NN)     + n4);
    float4 y2 = __ldg((const float4*)(rois + 3 * NN) + n4);

    // Fold x-mask into y-range: if w outside [x1,x2], empty the y-range.
    if (!(wf >= x1.x && wf <= x2.x)) y1.x = CUDART_INF_F;
    if (!(wf >= x1.y && wf <= x2.y)) y1.y = CUDART_INF_F;
    if (!(wf >= x1.z && wf <= x2.z)) y1.z = CUDART_INF_F;
    if (!(wf >= x1.w && wf <= x2.w)) y1.w = CUDART_INF_F;

    const int h0 = blockIdx.y * H_PER;
    const long base = (long)h0 * ROW4 + tid;
    const float4* __restrict__ pbase = data + base;

    // Phase 0: masks for all 8 rows.
    unsigned m[H_PER];
    #pragma unroll
    for (int i = 0; i < H_PER; ++i) {
        const float hf = (float)(h0 + i);
        m[i] = ((hf >= y1.x && hf <= y2.x) ? 1u : 0u)
             | ((hf >= y1.y && hf <= y2.y) ? 2u : 0u)
             | ((hf >= y1.z && hf <= y2.z) ? 4u : 0u)
             | ((hf >= y1.w && hf <= y2.w) ? 8u : 0u);
    }

    // Phase 1: 8 predicated loads in flight, single base reg + imm offsets.
    float4 v[H_PER];
    LDG_CS_PRED_OFF(v[0], m[0], pbase, 0);
    LDG_CS_PRED_OFF(v[1], m[1], pbase, 1);
    LDG_CS_PRED_OFF(v[2], m[2], pbase, 2);
    LDG_CS_PRED_OFF(v[3], m[3], pbase, 3);
    LDG_CS_PRED_OFF(v[4], m[4], pbase, 4);
    LDG_CS_PRED_OFF(v[5], m[5], pbase, 5);
    LDG_CS_PRED_OFF(v[6], m[6], pbase, 6);
    LDG_CS_PRED_OFF(v[7], m[7], pbase, 7);

    // Phase 2: blend (zeroes garbage lanes/components) + dense stores.
    float4* __restrict__ obase = out + base;
    #pragma unroll
    for (int i = 0; i < H_PER; ++i) {
        float4 r;
        r.x = (m[i] & 1u) ? v[i].x : 0.0f;
        r.y = (m[i] & 2u) ? v[i].y : 0.0f;
        r.z = (m[i] & 4u) ? v[i].z : 0.0f;
        r.w = (m[i] & 8u) ? v[i].w : 0.0f;
        __stcs(obase + (long)i * ROW4, r);
    }
}

extern "C" void kernel_launch(void* const* d_in, const int* in_sizes, int n_in,
                              void* d_out, int out_size)
{
    const float4* data = (const float4*)d_in[0];
    const float*  rois = (const float*)d_in[1];
    float4* out = (float4*)d_out;

    dim3 block(128);
    dim3 grid(ROW4 / 128, GY);   // 400 x 64 blocks
    crop_split_gt_kernel<<<grid, block>>>(data, rois, out);
}

// round 8
// speedup vs baseline: 1.2041x; 1.0034x over previous
#include <cuda_runtime.h>
#include <cuda_bf16.h>
#include <math_constants.h>

// CropSplitGT: out[h, w, n] = data[h, w, n] if (w,h) inside roi box n else 0.
// data (H, W, N) row-major, rois (4, N) = [x1; y1; x2; y2].
//
// Sparse-read, branch-free, MLP-8, register-lean:
//  - per-component ROW-INTERVAL -> 8-bit mask built once (no per-row FSETP);
//    all 32 mask bits live in ONE register (mpack), plus one 'any' byte.
//  - 8 predicated ld.global.cs.v4 with immediate row offsets (no per-load
//    address regs); garbage when pred false, blend forces 0.
//  - dense .cs stores (all outputs must be written).

#define HH 512
#define WW 512
#define NN 400
#define N4 (NN / 4)            // 100 float4 per pixel
#define ROW4 (WW * N4)         // 51200 float4 per row
#define ROWB 819200L           // row stride in BYTES
#define H_PER 8
#define GY (HH / H_PER)        // 64

// Predicated 128-bit streaming load at [base + literal byte offset].
// Contents UNDEFINED when pred==0; caller's blend masks them.
#define LDG_CS_PRED_OFF(dst, pred, base, I)                              \
    asm("{\n\t"                                                          \
        ".reg .pred %%pp;\n\t"                                           \
        "setp.ne.u32 %%pp, %4, 0;\n\t"                                   \
        "@%%pp ld.global.cs.v4.f32 {%0, %1, %2, %3}, [%5 + %6];\n\t"     \
        "}"                                                              \
        : "=f"((dst).x), "=f"((dst).y), "=f"((dst).z), "=f"((dst).w)     \
        : "r"(pred), "l"(base), "n"((I) * ROWB))

// 8-bit mask of rows i in [0,8) with (h0+i) in [y1, y2] (inclusive).
// y1 == +inf (x-miss fold) yields 0. All clamps keep shifts in [0,8].
__device__ __forceinline__ unsigned row_mask(float y1, float y2, float h0f)
{
    int ilo = __float2int_ru(y1 - h0f);   // saturates on +inf
    int ihi = __float2int_rd(y2 - h0f);
    ilo = max(ilo, 0);  ilo = min(ilo, 8);
    ihi = min(ihi, 7);  ihi = max(ihi, -1);
    return ((1u << (ihi + 1)) - 1u) & ~((1u << ilo) - 1u);
}

__global__ __launch_bounds__(128) void crop_split_gt_kernel(
    const float4* __restrict__ data,
    const float*  __restrict__ rois,
    float4*       __restrict__ out)
{
    const int tid = blockIdx.x * 128 + threadIdx.x;   // [0, ROW4) exactly
    const int w   = tid / N4;
    const int n4  = tid - w * N4;
    const float wf = (float)w;

    const float4 x1 = __ldg((const float4*)(rois)          + n4);
    const float4 x2 = __ldg((const float4*)(rois + 2 * NN) + n4);
    float4 y1 = __ldg((const float4*)(rois + NN)     + n4);
    float4 y2 = __ldg((const float4*)(rois + 3 * NN) + n4);

    // Fold x-mask into y-range: outside [x1,x2] -> empty interval.
    if (!(wf >= x1.x && wf <= x2.x)) y1.x = CUDART_INF_F;
    if (!(wf >= x1.y && wf <= x2.y)) y1.y = CUDART_INF_F;
    if (!(wf >= x1.z && wf <= x2.z)) y1.z = CUDART_INF_F;
    if (!(wf >= x1.w && wf <= x2.w)) y1.w = CUDART_INF_F;

    const int h0 = blockIdx.y * H_PER;
    const float h0f = (float)h0;

    // One register holds all 32 mask bits: byte c = rows mask of component c.
    const unsigned m0 = row_mask(y1.x, y2.x, h0f);
    const unsigned m1 = row_mask(y1.y, y2.y, h0f);
    const unsigned m2 = row_mask(y1.z, y2.z, h0f);
    const unsigned m3 = row_mask(y1.w, y2.w, h0f);
    const unsigned mpack = m0 | (m1 << 8) | (m2 << 16) | (m3 << 24);
    const unsigned anyb  = m0 | m1 | m2 | m3;   // row i needs a read iff bit i

    const long base = (long)h0 * ROW4 + tid;
    const float4* __restrict__ pbase = data + base;

    // Phase 1: 8 predicated loads in flight (imm offsets, one base reg).
    float4 v[H_PER];
    LDG_CS_PRED_OFF(v[0], anyb & 0x01u, pbase, 0);
    LDG_CS_PRED_OFF(v[1], anyb & 0x02u, pbase, 1);
    LDG_CS_PRED_OFF(v[2], anyb & 0x04u, pbase, 2);
    LDG_CS_PRED_OFF(v[3], anyb & 0x08u, pbase, 3);
    LDG_CS_PRED_OFF(v[4], anyb & 0x10u, pbase, 4);
    LDG_CS_PRED_OFF(v[5], anyb & 0x20u, pbase, 5);
    LDG_CS_PRED_OFF(v[6], anyb & 0x40u, pbase, 6);
    LDG_CS_PRED_OFF(v[7], anyb & 0x80u, pbase, 7);

    // Phase 2: blend from mpack bits + dense stores.
    float4* __restrict__ obase = out + base;
    #pragma unroll
    for (int i = 0; i < H_PER; ++i) {
        const unsigned t = mpack >> i;
        float4 r;
        r.x = (t & 0x00000001u) ? v[i].x : 0.0f;
        r.y = (t & 0x00000100u) ? v[i].y : 0.0f;
        r.z = (t & 0x00010000u) ? v[i].z : 0.0f;
        r.w = (t & 0x01000000u) ? v[i].w : 0.0f;
        __stcs(obase + (long)i * ROW4, r);
    }
}

extern "C" void kernel_launch(void* const* d_in, const int* in_sizes, int n_in,
                              void* d_out, int out_size)
{
    const float4* data = (const float4*)d_in[0];
    const float*  rois = (const float*)d_in[1];
    float4* out = (float4*)d_out;

    dim3 block(128);
    dim3 grid(ROW4 / 128, GY);   // 400 x 64 blocks
    crop_split_gt_kernel<<<grid, block>>>(data, rois, out);
}